// round 16
// baseline (speedup 1.0000x reference)
#include <cuda_runtime.h>
#include <cstdint>

#define BB 64
#define TT 512
#define HH 768
#define KK 11
#define START_ID 9
#define END_ID 10
#define NEGV (-10000.0f)
#define NROWS (BB*TT)            // 32768

#define GRID 148
#define THREADS 512

__device__ __align__(16) float g_feats[NROWS * KK];
__device__ int g_done = 0;       // monotonic across graph replays

// ---- dynamic smem layout (bytes). Phase A uses [0,33792) as sWt; Phase B+
// reuses it (barrier-separated aliasing).
#define OFF_SDELTA 0             // float[512*12]          = 24576
#define OFF_SFEAT  24576         // float[(512+12)*11]     = 23056
#define OFF_STRANS 47632         // float[121]
#define OFF_PSEG   48128         // uchar[16*11][32]       = 5632
#define OFF_ESEL   53760
#define OFF_LT     53776
#define SMEM_TOTAL 55296

extern __shared__ char dsm[];

// ---------------------------------------------------------------------------
// psi recompute: argmax_j (trans[tag][j] + delta[t-1][j]), first-max wins.
// Only j=0..8 can win for t>=2; at t=1 winner is START. Bit-exact.
// ---------------------------------------------------------------------------
__device__ __forceinline__ int psi_step(const float* __restrict__ strans,
                                        const float* __restrict__ sdelta,
                                        int t, int tag)
{
    if (t == 1) return START_ID;
    const float* tr = strans + tag * KK;
    const float* d = sdelta + (t - 1) * 12;
    float s[9];
#pragma unroll
    for (int j = 0; j < 9; j++) s[j] = tr[j] + d[j];
    float m = s[0];
#pragma unroll
    for (int j = 1; j < 9; j++) m = fmaxf(m, s[j]);
    unsigned msk = 0;
#pragma unroll
    for (int j = 0; j < 9; j++) msk |= (s[j] == m) ? (1u << j) : 0u;
    return __ffs(msk) - 1;
}

// ---------------------------------------------------------------------------
__global__ __launch_bounds__(THREADS, 1) void mono_kernel(
    const float* __restrict__ embeds,   // [B,T,H]
    const float* __restrict__ W,        // [K,H]
    const float* __restrict__ bias,     // [K]
    const float* __restrict__ trans,    // [K,K]
    float* __restrict__ out)            // [B + B*T]
{
    const int bid = blockIdx.x;
    const int tid = threadIdx.x;
    const int wid = tid >> 5;
    const int lane = tid & 31;

    // ========================= PHASE A: feats GEMM =========================
    {
        float* sWt = (float*)dsm;       // [h*11 + k]
        for (int i = tid; i < KK * HH; i += THREADS) {
            int k = i / HH, h = i - k * HH;
            sWt[h * KK + k] = W[i];
        }
        const float breg = (lane < KK) ? __ldg(&bias[lane]) : 0.0f;
        __syncthreads();

        // pass map: passes 0..511 of 64 rows. All blocks: bid, bid+148,
        // bid+296. Leftover passes 444..511 -> producer blocks 64..131.
        int q[4]; int nq = 3;
        q[0] = bid; q[1] = bid + 148; q[2] = bid + 296;
        if (bid >= 64 && bid < 132) { q[3] = 444 + (bid - 64); nq = 4; }

        for (int pi = 0; pi < nq; ++pi) {
            const int rowBase = q[pi] * 64 + wid * 4;
            const float* Ab = embeds + (size_t)rowBase * HH;

            float acc[4][KK];
#pragma unroll
            for (int r = 0; r < 4; r++)
#pragma unroll
                for (int k = 0; k < KK; k++) acc[r][k] = 0.0f;

            float a[4][4], na[4][4];
#pragma unroll
            for (int r = 0; r < 4; r++)
#pragma unroll
                for (int s = 0; s < 4; s++)
                    a[r][s] = Ab[(size_t)r * HH + s * 32 + lane];

#pragma unroll
            for (int w = 0; w < 6; w++) {
                if (w < 5) {
#pragma unroll
                    for (int r = 0; r < 4; r++)
#pragma unroll
                        for (int s = 0; s < 4; s++)
                            na[r][s] = Ab[(size_t)r * HH + (w + 1) * 128 + s * 32 + lane];
                }
#pragma unroll
                for (int s = 0; s < 4; s++) {
                    float wr[KK];
                    const int hb = (w * 128 + s * 32 + lane) * KK;
#pragma unroll
                    for (int k = 0; k < KK; k++) wr[k] = sWt[hb + k];
#pragma unroll
                    for (int r = 0; r < 4; r++)
#pragma unroll
                        for (int k = 0; k < KK; k++)
                            acc[r][k] = fmaf(a[r][s], wr[k], acc[r][k]);
                }
#pragma unroll
                for (int r = 0; r < 4; r++)
#pragma unroll
                    for (int s = 0; s < 4; s++) a[r][s] = na[r][s];
            }

            // butterfly-reduce; lane k keeps column k (select, no dyn index)
            float outv[4];
#pragma unroll
            for (int k = 0; k < KK; k++) {
#pragma unroll
                for (int r = 0; r < 4; r++) {
                    float v = acc[r][k];
                    v += __shfl_xor_sync(0xffffffffu, v, 16);
                    v += __shfl_xor_sync(0xffffffffu, v, 8);
                    v += __shfl_xor_sync(0xffffffffu, v, 4);
                    v += __shfl_xor_sync(0xffffffffu, v, 2);
                    v += __shfl_xor_sync(0xffffffffu, v, 1);
                    if (lane == k) outv[r] = v + breg;
                }
            }
            if (lane < KK) {
#pragma unroll
                for (int r = 0; r < 4; r++)
                    g_feats[(size_t)(rowBase + r) * KK + lane] = outv[r];
            }
        }
        __syncthreads();

        // -------- replay-safe grid barrier (monotonic counter) --------
        if (tid == 0) {
            __threadfence();                       // release g_feats writes
            int old = atomicAdd(&g_done, 1);
            if (bid < 64) {
                int target = old - (old % GRID) + GRID;
                while (*(volatile int*)&g_done < target) {}
                __threadfence();                   // acquire
            }
        }
        if (bid >= 64) return;                     // producers done
        __syncthreads();                           // broadcast barrier pass
    }

    // ==================== PHASE B: stage (scan blocks) =====================
    const int b = bid;
    float* sdelta = (float*)(dsm + OFF_SDELTA);
    float* sfeat  = (float*)(dsm + OFF_SFEAT);     // [t*11 + k]
    float* strans = (float*)(dsm + OFF_STRANS);
    unsigned char (*pseg)[32] = (unsigned char (*)[32])(dsm + OFF_PSEG);
    unsigned char* esel = (unsigned char*)(dsm + OFF_ESEL);
    int* s_lt = (int*)(dsm + OFF_LT);

    {
        const float4* fsrc = (const float4*)(g_feats + (size_t)b * TT * KK);
        float4* fdst = (float4*)sfeat;
        for (int i = tid; i < (TT * KK) / 4; i += THREADS)
            fdst[i] = __ldcg(&fsrc[i]);            // first touch, L2-coherent
        for (int i = tid; i < KK * KK; i += THREADS) strans[i] = trans[i];
    }
    __syncthreads();

    // ======================= PHASE C: scan (warp 0) ========================
    if (wid == 0) {
        const int target = (lane <= 8) ? lane : END_ID;
        const int slot4 = ((lane <= 8) ? lane : 9) * 4;

        float tr0 = strans[target * KK + 0], tr1 = strans[target * KK + 1];
        float tr2 = strans[target * KK + 2], tr3 = strans[target * KK + 3];
        float tr4 = strans[target * KK + 4], tr5 = strans[target * KK + 5];
        float tr6 = strans[target * KK + 6], tr7 = strans[target * KK + 7];
        float tr8 = strans[target * KK + 8], tr9 = strans[target * KK + 9];

        const unsigned sd_base = (unsigned)__cvta_generic_to_shared(sdelta);
        const unsigned sf_base = (unsigned)__cvta_generic_to_shared(sfeat);

        float d0, d1, d2, d3, d4, d5, d6, d7, d8;

        // ---- t = 1 closed form: predecessor is START (certain) ----
        {
            float f1;
            asm volatile("ld.shared.f32 %0, [%1];"
                         : "=f"(f1) : "r"(sf_base + (KK + target) * 4));
            float nd1 = (tr9 + 0.0f) + f1;
            unsigned row1 = sd_base + 48;
            asm volatile("st.shared.f32 [%0], %1;"
                         :: "r"(row1 + slot4), "f"(nd1) : "memory");
            asm volatile("ld.shared.v4.f32 {%0,%1,%2,%3}, [%4];"
                         : "=f"(d0), "=f"(d1), "=f"(d2), "=f"(d3)
                         : "r"(row1) : "memory");
            asm volatile("ld.shared.v4.f32 {%0,%1,%2,%3}, [%4+16];"
                         : "=f"(d4), "=f"(d5), "=f"(d6), "=f"(d7)
                         : "r"(row1) : "memory");
            asm volatile("ld.shared.f32 %0, [%1+32];"
                         : "=f"(d8) : "r"(row1) : "memory");
        }

        float fbuf[6];
#pragma unroll
        for (int s = 0; s < 6; s++)
            asm volatile("ld.shared.f32 %0, [%1];"
                         : "=f"(fbuf[s]) : "r"(sf_base + ((2 + s) * KK + target) * 4));
        unsigned fpre = sf_base + (8 * KK + target) * 4;

        unsigned addr = sd_base + 96;              // row 2
        unsigned sd_store = addr + slot4;

#define VSTEP(U_, O0, O1)                                                      \
        {                                                                      \
            float f = fbuf[U_];                                                \
            float s0 = tr0 + d0, s1 = tr1 + d1, s2 = tr2 + d2, s3 = tr3 + d3;  \
            float s4 = tr4 + d4, s5 = tr5 + d5, s6 = tr6 + d6, s7 = tr7 + d7;  \
            float s8v = tr8 + d8;                                              \
            float m01 = fmaxf(s0, s1), m23 = fmaxf(s2, s3);                    \
            float m45 = fmaxf(s4, s5), m67 = fmaxf(s6, s7);                    \
            float m = fmaxf(fmaxf(fmaxf(m01, m23), fmaxf(m45, m67)), s8v);     \
            float nd = m + f;                                                  \
            asm volatile("st.shared.f32 [%0+" #O0 "], %1;"                     \
                         :: "r"(sd_store), "f"(nd) : "memory");                \
            asm volatile("ld.shared.v4.f32 {%0,%1,%2,%3}, [%4+" #O0 "];"       \
                         : "=f"(d0), "=f"(d1), "=f"(d2), "=f"(d3)              \
                         : "r"(addr) : "memory");                              \
            asm volatile("ld.shared.v4.f32 {%0,%1,%2,%3}, [%4+" #O1 "];"       \
                         : "=f"(d4), "=f"(d5), "=f"(d6), "=f"(d7)              \
                         : "r"(addr) : "memory");                              \
            asm volatile("ld.shared.f32 %0, [%1+" #O1 "+16];"                  \
                         : "=f"(d8) : "r"(addr) : "memory");                   \
            asm volatile("ld.shared.f32 %0, [%1];"                             \
                         : "=f"(fbuf[U_]) : "r"(fpre));                        \
            fpre += 44;                                                        \
        }

        for (int it = 0; it < 85; ++it) {          // 85*6 = 510 steps, t=2..511
            VSTEP(0, 0, 16)
            VSTEP(1, 48, 64)
            VSTEP(2, 96, 112)
            VSTEP(3, 144, 160)
            VSTEP(4, 192, 208)
            VSTEP(5, 240, 256)
            addr += 288;
            sd_store += 288;
        }
#undef VSTEP

        __syncwarp();
        float dEND = sdelta[511 * 12 + 9];

        {
            float m01 = fmaxf(d0, d1), m23 = fmaxf(d2, d3);
            float m45 = fmaxf(d4, d5), m67 = fmaxf(d6, d7);
            float m = fmaxf(fmaxf(fmaxf(m01, m23), fmaxf(m45, m67)),
                            fmaxf(d8, dEND));
            unsigned msk = (d0 == m ? 1u : 0u) | (d1 == m ? 2u : 0u) |
                           (d2 == m ? 4u : 0u) | (d3 == m ? 8u : 0u) |
                           (d4 == m ? 16u : 0u) | (d5 == m ? 32u : 0u) |
                           (d6 == m ? 64u : 0u) | (d7 == m ? 128u : 0u) |
                           (d8 == m ? 256u : 0u) |
                           (dEND == m ? (1u << END_ID) : 0u);
            if (lane == 0) {
                out[b] = m;                        // score
                *s_lt = __ffs(msk) - 1;
            }
        }
    }
    __syncthreads();

    // ================= PHASE D: backtrack (psi recompute) ==================
    if (tid < 165) {                       // chunks 0..14 x 11 entry tags
        const int c = tid / KK;
        const int e = tid - c * KK;
        const int tb = 32 * c;
        int tag = e;
        for (int t = tb + 32; t > tb; --t) {
            tag = psi_step(strans, sdelta, t, tag);
            pseg[c * KK + e][t - 1 - tb] = (unsigned char)tag;
        }
    } else if (tid == 165) {               // chunk 15 from known last tag
        int tag = *s_lt;
        pseg[15 * KK][31] = (unsigned char)tag;
        for (int t = TT - 1; t > 480; --t) {
            tag = psi_step(strans, sdelta, t, tag);
            pseg[15 * KK][t - 1 - 480] = (unsigned char)tag;
        }
    }
    __syncthreads();

    if (tid == 0) {
        esel[15] = 0;
        int btag = pseg[15 * KK][0];       // tag at position 480
        for (int c = 14; c >= 0; --c) {
            esel[c] = (unsigned char)btag;
            btag = pseg[c * KK + btag][0];
        }
    }
    __syncthreads();

    for (int p = tid; p < TT; p += THREADS) {
        int c = p >> 5;
        out[BB + (size_t)b * TT + p] = (float)pseg[c * KK + esel[c]][p & 31];
    }
}

// ---------------------------------------------------------------------------
extern "C" void kernel_launch(void* const* d_in, const int* in_sizes, int n_in,
                              void* d_out, int out_size)
{
    const float* embeds = (const float*)d_in[0];   // [B,T,H]
    const float* W_fc   = (const float*)d_in[1];   // [K,H]
    const float* b_fc   = (const float*)d_in[2];   // [K]
    const float* trans  = (const float*)d_in[3];   // [K,K]
    float* out = (float*)d_out;

    cudaFuncSetAttribute(mono_kernel,
                         cudaFuncAttributeMaxDynamicSharedMemorySize, SMEM_TOTAL);
    mono_kernel<<<GRID, THREADS, SMEM_TOTAL>>>(embeds, W_fc, b_fc, trans, out);
}

// round 17
// speedup vs baseline: 2.1411x; 2.1411x over previous
#include <cuda_runtime.h>
#include <cstdint>

#define BB 64
#define TT 512
#define HH 768
#define KK 11
#define START_ID 9
#define END_ID 10
#define NEGV (-10000.0f)
#define NROWS (BB*TT)            // 32768

#define GRID 148
#define THREADS 512

__device__ __align__(16) float g_feats[NROWS * KK];
__device__ int g_done = 0;       // monotonic across graph replays

// ---- dynamic smem layout (bytes). Phase A uses [0,33792) as sWt; Phase B+
// reuses it (barrier-separated aliasing).
#define OFF_SDELTA 0             // float[512*12]          = 24576
#define OFF_SFEAT  24576         // float[(512+12)*11]     = 23056
#define OFF_STRANS 47632         // float[121]
#define OFF_PSEG   48128         // uchar[16*11][32]       = 5632
#define OFF_ESEL   53760
#define OFF_LT     53776
#define SMEM_TOTAL 55296

extern __shared__ char dsm[];

// ---------------------------------------------------------------------------
// psi recompute: argmax_j (trans[tag][j] + delta[t-1][j]), first-max wins.
// Only j=0..8 can win for t>=2; at t=1 winner is START. Bit-exact.
// ---------------------------------------------------------------------------
__device__ __forceinline__ int psi_step(const float* __restrict__ strans,
                                        const float* __restrict__ sdelta,
                                        int t, int tag)
{
    if (t == 1) return START_ID;
    const float* tr = strans + tag * KK;
    const float* d = sdelta + (t - 1) * 12;
    float s[9];
#pragma unroll
    for (int j = 0; j < 9; j++) s[j] = tr[j] + d[j];
    float m = s[0];
#pragma unroll
    for (int j = 1; j < 9; j++) m = fmaxf(m, s[j]);
    unsigned msk = 0;
#pragma unroll
    for (int j = 0; j < 9; j++) msk |= (s[j] == m) ? (1u << j) : 0u;
    return __ffs(msk) - 1;
}

// ---------------------------------------------------------------------------
__global__ __launch_bounds__(THREADS, 1) void mono_kernel(
    const float* __restrict__ embeds,   // [B,T,H]
    const float* __restrict__ W,        // [K,H]
    const float* __restrict__ bias,     // [K]
    const float* __restrict__ trans,    // [K,K]
    float* __restrict__ out)            // [B + B*T]
{
    const int bid = blockIdx.x;
    const int tid = threadIdx.x;
    const int wid = tid >> 5;
    const int lane = tid & 31;

    // ========================= PHASE A: feats GEMM =========================
    // 1024 passes of 32 rows; each block takes p = bid, bid+148, ... (<=7).
    // 2 rows/thread, float4 double-buffered loads (low reg pressure, no spill).
    {
        float* sWt = (float*)dsm;       // [h*11 + k]
        for (int i = tid; i < KK * HH; i += THREADS) {
            int k = i / HH, h = i - k * HH;
            sWt[h * KK + k] = W[i];
        }
        __syncthreads();

        for (int p = bid; p < 1024; p += GRID) {
            const int rowBase = p * 32 + wid * 2;
            const float4* A0 = (const float4*)(embeds + (size_t)rowBase * HH);
            const float4* A1 = (const float4*)(embeds + (size_t)(rowBase + 1) * HH);

            float acc0[KK], acc1[KK];
#pragma unroll
            for (int k = 0; k < KK; k++) { acc0[k] = 0.0f; acc1[k] = 0.0f; }

            float4 c0 = A0[lane], c1 = A1[lane];
            float4 n0, n1;

#pragma unroll
            for (int w = 0; w < 6; w++) {
                if (w < 5) {
                    n0 = A0[(w + 1) * 32 + lane];
                    n1 = A1[(w + 1) * 32 + lane];
                }
#pragma unroll
                for (int e = 0; e < 4; e++) {
                    const float a0e = (e == 0) ? c0.x : (e == 1) ? c0.y : (e == 2) ? c0.z : c0.w;
                    const float a1e = (e == 0) ? c1.x : (e == 1) ? c1.y : (e == 2) ? c1.z : c1.w;
                    const int hb = (((w * 32 + lane) << 2) + e) * KK;
#pragma unroll
                    for (int k = 0; k < KK; k++) {
                        const float wv = sWt[hb + k];
                        acc0[k] = fmaf(a0e, wv, acc0[k]);
                        acc1[k] = fmaf(a1e, wv, acc1[k]);
                    }
                }
                c0 = n0; c1 = n1;
            }

            // butterfly-reduce the 22 partials (result in all lanes)
#pragma unroll
            for (int k = 0; k < KK; k++) {
                float v0 = acc0[k], v1 = acc1[k];
#pragma unroll
                for (int off = 16; off > 0; off >>= 1) {
                    v0 += __shfl_xor_sync(0xffffffffu, v0, off);
                    v1 += __shfl_xor_sync(0xffffffffu, v1, off);
                }
                acc0[k] = v0; acc1[k] = v1;
            }

            if (lane < KK) {
                const float bk = __ldg(&bias[lane]);
                // lane k writes column k of both rows (coalesced-ish, 22 STGs)
                float o0 = 0.f, o1 = 0.f;
#pragma unroll
                for (int k = 0; k < KK; k++)
                    if (lane == k) { o0 = acc0[k]; o1 = acc1[k]; }
                g_feats[(size_t)rowBase * KK + lane] = o0 + bk;
                g_feats[(size_t)(rowBase + 1) * KK + lane] = o1 + bk;
            }
        }
        __syncthreads();

        // -------- replay-safe grid barrier (monotonic counter) --------
        if (tid == 0) {
            __threadfence();                       // release g_feats writes
            int old = atomicAdd(&g_done, 1);
            if (bid < 64) {
                int target = old - (old % GRID) + GRID;
                while (*(volatile int*)&g_done < target) {}
                __threadfence();                   // acquire
            }
        }
        if (bid >= 64) return;                     // producers done
        __syncthreads();                           // broadcast barrier pass
    }

    // ==================== PHASE B: stage (scan blocks) =====================
    const int b = bid;
    float* sdelta = (float*)(dsm + OFF_SDELTA);
    float* sfeat  = (float*)(dsm + OFF_SFEAT);     // [t*11 + k]
    float* strans = (float*)(dsm + OFF_STRANS);
    unsigned char (*pseg)[32] = (unsigned char (*)[32])(dsm + OFF_PSEG);
    unsigned char* esel = (unsigned char*)(dsm + OFF_ESEL);
    int* s_lt = (int*)(dsm + OFF_LT);

    {
        const float4* fsrc = (const float4*)(g_feats + (size_t)b * TT * KK);
        float4* fdst = (float4*)sfeat;
        for (int i = tid; i < (TT * KK) / 4; i += THREADS)
            fdst[i] = __ldcg(&fsrc[i]);            // first touch, L2-coherent
        for (int i = tid; i < KK * KK; i += THREADS) strans[i] = trans[i];
    }
    __syncthreads();

    // ======================= PHASE C: scan (warp 0) ========================
    if (wid == 0) {
        const int target = (lane <= 8) ? lane : END_ID;
        const int slot4 = ((lane <= 8) ? lane : 9) * 4;

        float tr0 = strans[target * KK + 0], tr1 = strans[target * KK + 1];
        float tr2 = strans[target * KK + 2], tr3 = strans[target * KK + 3];
        float tr4 = strans[target * KK + 4], tr5 = strans[target * KK + 5];
        float tr6 = strans[target * KK + 6], tr7 = strans[target * KK + 7];
        float tr8 = strans[target * KK + 8], tr9 = strans[target * KK + 9];

        const unsigned sd_base = (unsigned)__cvta_generic_to_shared(sdelta);
        const unsigned sf_base = (unsigned)__cvta_generic_to_shared(sfeat);

        float d0, d1, d2, d3, d4, d5, d6, d7, d8;

        // ---- t = 1 closed form: predecessor is START (certain) ----
        {
            float f1;
            asm volatile("ld.shared.f32 %0, [%1];"
                         : "=f"(f1) : "r"(sf_base + (KK + target) * 4));
            float nd1 = (tr9 + 0.0f) + f1;
            unsigned row1 = sd_base + 48;
            asm volatile("st.shared.f32 [%0], %1;"
                         :: "r"(row1 + slot4), "f"(nd1) : "memory");
            asm volatile("ld.shared.v4.f32 {%0,%1,%2,%3}, [%4];"
                         : "=f"(d0), "=f"(d1), "=f"(d2), "=f"(d3)
                         : "r"(row1) : "memory");
            asm volatile("ld.shared.v4.f32 {%0,%1,%2,%3}, [%4+16];"
                         : "=f"(d4), "=f"(d5), "=f"(d6), "=f"(d7)
                         : "r"(row1) : "memory");
            asm volatile("ld.shared.f32 %0, [%1+32];"
                         : "=f"(d8) : "r"(row1) : "memory");
        }

        float fbuf[6];
#pragma unroll
        for (int s = 0; s < 6; s++)
            asm volatile("ld.shared.f32 %0, [%1];"
                         : "=f"(fbuf[s]) : "r"(sf_base + ((2 + s) * KK + target) * 4));
        unsigned fpre = sf_base + (8 * KK + target) * 4;

        unsigned addr = sd_base + 96;              // row 2
        unsigned sd_store = addr + slot4;

#define VSTEP(U_, O0, O1)                                                      \
        {                                                                      \
            float f = fbuf[U_];                                                \
            asm volatile("ld.shared.f32 %0, [%1];"                             \
                         : "=f"(fbuf[U_]) : "r"(fpre));                        \
            fpre += 44;                                                        \
            float s0 = tr0 + d0, s1 = tr1 + d1, s2 = tr2 + d2, s3 = tr3 + d3;  \
            float s4 = tr4 + d4, s5 = tr5 + d5, s6 = tr6 + d6, s7 = tr7 + d7;  \
            float s8v = tr8 + d8;                                              \
            float m01 = fmaxf(s0, s1), m23 = fmaxf(s2, s3);                    \
            float m45 = fmaxf(s4, s5), m67 = fmaxf(s6, s7);                    \
            float m = fmaxf(fmaxf(fmaxf(m01, m23), fmaxf(m45, m67)), s8v);     \
            float nd = m + f;                                                  \
            asm volatile("st.shared.f32 [%0+" #O0 "], %1;"                     \
                         :: "r"(sd_store), "f"(nd) : "memory");                \
            asm volatile("ld.shared.v4.f32 {%0,%1,%2,%3}, [%4+" #O0 "];"       \
                         : "=f"(d0), "=f"(d1), "=f"(d2), "=f"(d3)              \
                         : "r"(addr) : "memory");                              \
            asm volatile("ld.shared.v4.f32 {%0,%1,%2,%3}, [%4+" #O1 "];"       \
                         : "=f"(d4), "=f"(d5), "=f"(d6), "=f"(d7)              \
                         : "r"(addr) : "memory");                              \
            asm volatile("ld.shared.f32 %0, [%1+" #O1 "+16];"                  \
                         : "=f"(d8) : "r"(addr) : "memory");                   \
        }

        for (int it = 0; it < 85; ++it) {          // 85*6 = 510 steps, t=2..511
            VSTEP(0, 0, 16)
            VSTEP(1, 48, 64)
            VSTEP(2, 96, 112)
            VSTEP(3, 144, 160)
            VSTEP(4, 192, 208)
            VSTEP(5, 240, 256)
            addr += 288;
            sd_store += 288;
        }
#undef VSTEP

        __syncwarp();
        float dEND = sdelta[511 * 12 + 9];

        {
            float m01 = fmaxf(d0, d1), m23 = fmaxf(d2, d3);
            float m45 = fmaxf(d4, d5), m67 = fmaxf(d6, d7);
            float m = fmaxf(fmaxf(fmaxf(m01, m23), fmaxf(m45, m67)),
                            fmaxf(d8, dEND));
            unsigned msk = (d0 == m ? 1u : 0u) | (d1 == m ? 2u : 0u) |
                           (d2 == m ? 4u : 0u) | (d3 == m ? 8u : 0u) |
                           (d4 == m ? 16u : 0u) | (d5 == m ? 32u : 0u) |
                           (d6 == m ? 64u : 0u) | (d7 == m ? 128u : 0u) |
                           (d8 == m ? 256u : 0u) |
                           (dEND == m ? (1u << END_ID) : 0u);
            if (lane == 0) {
                out[b] = m;                        // score
                *s_lt = __ffs(msk) - 1;
            }
        }
    }
    __syncthreads();

    // ================= PHASE D: backtrack (psi recompute) ==================
    if (tid < 165) {                       // chunks 0..14 x 11 entry tags
        const int c = tid / KK;
        const int e = tid - c * KK;
        const int tb = 32 * c;
        int tag = e;
        for (int t = tb + 32; t > tb; --t) {
            tag = psi_step(strans, sdelta, t, tag);
            pseg[c * KK + e][t - 1 - tb] = (unsigned char)tag;
        }
    } else if (tid == 165) {               // chunk 15 from known last tag
        int tag = *s_lt;
        pseg[15 * KK][31] = (unsigned char)tag;
        for (int t = TT - 1; t > 480; --t) {
            tag = psi_step(strans, sdelta, t, tag);
            pseg[15 * KK][t - 1 - 480] = (unsigned char)tag;
        }
    }
    __syncthreads();

    if (tid == 0) {
        esel[15] = 0;
        int btag = pseg[15 * KK][0];       // tag at position 480
        for (int c = 14; c >= 0; --c) {
            esel[c] = (unsigned char)btag;
            btag = pseg[c * KK + btag][0];
        }
    }
    __syncthreads();

    for (int p = tid; p < TT; p += THREADS) {
        int c = p >> 5;
        out[BB + (size_t)b * TT + p] = (float)pseg[c * KK + esel[c]][p & 31];
    }
}

// ---------------------------------------------------------------------------
extern "C" void kernel_launch(void* const* d_in, const int* in_sizes, int n_in,
                              void* d_out, int out_size)
{
    const float* embeds = (const float*)d_in[0];   // [B,T,H]
    const float* W_fc   = (const float*)d_in[1];   // [K,H]
    const float* b_fc   = (const float*)d_in[2];   // [K]
    const float* trans  = (const float*)d_in[3];   // [K,K]
    float* out = (float*)d_out;

    cudaFuncSetAttribute(mono_kernel,
                         cudaFuncAttributeMaxDynamicSharedMemorySize, SMEM_TOTAL);
    mono_kernel<<<GRID, THREADS, SMEM_TOTAL>>>(embeds, W_fc, b_fc, trans, out);
}